// round 16
// baseline (speedup 1.0000x reference)
#include <cuda_runtime.h>

#define FULL_MASK 0xffffffffu
#define NLOG2E (-1.4426950408889634f)   // -log2(e)

// sigmoid(x*scale), scale/log2e/sign folded: sigma = 1/(1+2^(x*c)).
// Same MUFU ops (EX2,RCP) the __expf/__fdividef path emits.
__device__ __forceinline__ float sigmoid_c(float x, float c) {
    float e, r;
    asm("ex2.approx.f32 %0, %1;" : "=f"(e) : "f"(x * c));
    asm("rcp.approx.f32 %0, %1;" : "=f"(r) : "f"(1.0f + e));
    return r;
}

// 256-bit global load, L2 evict_last (input biased to stay L2-resident).
__device__ __forceinline__ void ldg256_evl(const float* p, float v[8]) {
    unsigned r0,r1,r2,r3,r4,r5,r6,r7;
    asm volatile("ld.global.nc.L2::evict_last.v8.b32 {%0,%1,%2,%3,%4,%5,%6,%7}, [%8];"
        : "=r"(r0),"=r"(r1),"=r"(r2),"=r"(r3),
          "=r"(r4),"=r"(r5),"=r"(r6),"=r"(r7) : "l"(p));
    v[0]=__uint_as_float(r0); v[1]=__uint_as_float(r1);
    v[2]=__uint_as_float(r2); v[3]=__uint_as_float(r3);
    v[4]=__uint_as_float(r4); v[5]=__uint_as_float(r5);
    v[6]=__uint_as_float(r6); v[7]=__uint_as_float(r7);
}
// 256-bit global store, L2 evict_first (output streams through L2).
__device__ __forceinline__ void stg256_evf(float* p, const float v[8]) {
    asm volatile("st.global.L2::evict_first.v8.b32 [%0], {%1,%2,%3,%4,%5,%6,%7,%8};"
        :: "l"(p),
           "r"(__float_as_uint(v[0])), "r"(__float_as_uint(v[1])),
           "r"(__float_as_uint(v[2])), "r"(__float_as_uint(v[3])),
           "r"(__float_as_uint(v[4])), "r"(__float_as_uint(v[5])),
           "r"(__float_as_uint(v[6])), "r"(__float_as_uint(v[7]))
        : "memory");
}

// One warp per row of 1024 floats, complete binary tree depth 10.
// ZERO shared memory, zero syncs: chunk M = lane + 32k (k = quadrant).
// Quadrant k = d2-subtree [256k, 256k+256) = {chunk M : all lanes, fixed k}.
//   - levels d=6..2: per-quadrant 5-step shfl_xor butterfly over chunk sums
//     (each lane accumulates its own chunk's path probability),
//   - levels d=1,0: scalar sigmoids on the 4 quadrant totals (every lane
//     has all totals after the butterflies),
//   - levels d=7,8,9: in-register per chunk from diffs saved at load time.
// All global accesses are coalesced 256-bit (lane-adjacent addresses).
__global__ void __launch_bounds__(256, 4)
nbdt_kernel(const float* __restrict__ in, float* __restrict__ out)
{
    const int warp = threadIdx.x >> 5;
    const int lane = threadIdx.x & 31;
    const int row  = (blockIdx.x << 3) + warp;

    const float* rin  = in  + (size_t)row * 1024;
    float*       rout = out + (size_t)row * 1024;

    float d9[16], d8[8], d7[4], S[4];

    // ---- load + per-chunk partials (all in registers) ----
    #pragma unroll
    for (int k = 0; k < 4; k++) {
        int M = lane + (k << 5);
        float v[8];
        ldg256_evl(rin + (M << 3), v);
        float a0 = v[0]+v[1], a1 = v[2]+v[3], a2 = v[4]+v[5], a3 = v[6]+v[7];
        d9[4*k+0] = v[0]-v[1]; d9[4*k+1] = v[2]-v[3];
        d9[4*k+2] = v[4]-v[5]; d9[4*k+3] = v[6]-v[7];
        d8[2*k]   = a0 - a1;   d8[2*k+1] = a2 - a3;
        float b0 = a0 + a1, b1 = a2 + a3;
        d7[k] = b0 - b1;
        S[k]  = b0 + b1;                   // chunk sum (8 leaves)
    }

    // ---- per-quadrant butterflies: levels d=6..2 ----
    // step st pairs groups of 8*2^st leaves; prob = sigmoid(diff/blk).
    float acc[4];
    #pragma unroll
    for (int k = 0; k < 4; k++) {
        float s = S[k], a = 1.0f, cc = NLOG2E / 8.0f;
        #pragma unroll
        for (int st = 0; st < 5; st++) {
            float part = __shfl_xor_sync(FULL_MASK, s, 1 << st);
            a *= sigmoid_c(s - part, cc);
            s += part;
            cc *= 0.5f;
        }
        acc[k] = a;
        S[k] = s;                          // quadrant total (all lanes)
    }

    // ---- top levels d=0 (blk=512), d=1 (blk=256) ----
    float h0 = S[0] + S[1], h1 = S[2] + S[3];
    float pL = sigmoid_c(h0 - h1, NLOG2E / 512.0f);   // left half
    float pR = 1.0f - pL;
    float pdl = sigmoid_c(S[0] - S[1], NLOG2E / 256.0f);
    float pdr = sigmoid_c(S[2] - S[3], NLOG2E / 256.0f);
    float top[4];
    top[0] = pL * pdl;  top[1] = pL - top[0];
    top[2] = pR * pdr;  top[3] = pR - top[2];

    // ---- finish levels d=7,8,9 per chunk + coalesced 256-bit store ----
    #pragma unroll
    for (int k = 0; k < 4; k++) {
        int M = lane + (k << 5);
        float p   = top[k] * acc[k];
        float pl7 = sigmoid_c(d7[k], NLOG2E / 4.0f);
        float hi = p * pl7, lo = p - hi;
        float pa = sigmoid_c(d8[2*k], NLOG2E / 2.0f);
        float q0 = hi * pa, q1 = hi - q0;
        float pb = sigmoid_c(d8[2*k+1], NLOG2E / 2.0f);
        float q2 = lo * pb, q3 = lo - q2;
        float o[8];
        float t0 = sigmoid_c(d9[4*k+0], NLOG2E); o[0] = q0 * t0; o[1] = q0 - o[0];
        float t1 = sigmoid_c(d9[4*k+1], NLOG2E); o[2] = q1 * t1; o[3] = q1 - o[2];
        float t2 = sigmoid_c(d9[4*k+2], NLOG2E); o[4] = q2 * t2; o[5] = q2 - o[4];
        float t3 = sigmoid_c(d9[4*k+3], NLOG2E); o[6] = q3 * t3; o[7] = q3 - o[6];
        stg256_evf(rout + (M << 3), o);
    }
}

extern "C" void kernel_launch(void* const* d_in, const int* in_sizes, int n_in,
                              void* d_out, int out_size)
{
    const float* in = (const float*)d_in[0];
    float* out = (float*)d_out;
    int rows = in_sizes[0] / 1024;             // BATCH = 16384
    nbdt_kernel<<<rows / 8, 256>>>(in, out);
}